// round 6
// baseline (speedup 1.0000x reference)
#include <cuda_runtime.h>

// IndRNN recurrence: h_t = relu(h_{t-1} * w_hh + x_t), elementwise over
// 32*1024 = 32768 independent channels, 2048 timesteps.
// Pure streaming: 256 MB in + 256 MB out -> HBM-bound, floor ~64 us @ 8 TB/s.
//
// One thread per channel (warp-contiguous, 128B-aligned -> nL=1 loads).
// Recurrence serial in t; x[t] loads independent of h -> register
// ping-pong of UNROLL timesteps keeps 32 loads/thread in flight.
//
// History:
//  R3: launch_bounds reg cap killed MLP -> 370us, DRAM 16%.
//  R4: cap off, UNROLL=20 -> 112.7us, DRAM 54%.
//  R5: UNROLL=32 -> 100.4us, DRAM 62%. Sub-linear: queueing, not latency.
//      Found wave imbalance: 256 blocks on 148 SMs -> 108 SMs do 2 blocks,
//      40 idle half the time. Busy-SM rate 42 GB/s vs 54 GB/s fair share.
//  R6: balance at one block/SM: 147 blocks x 224 threads (224 = 7 warps,
//      multiple of 32 -> aligned coalescing). Per-SM path 256->224 ch.

constexpr int LEN    = 2048;
constexpr int BATCH  = 32;
constexpr int HIDDEN = 1024;
constexpr int NCH    = BATCH * HIDDEN;   // 32768 channels
constexpr int UNROLL = 32;               // timesteps per buffer half
static_assert(LEN % (2 * UNROLL) == 0, "exact tiling, no tail");

constexpr int THREADS = 224;             // 7 warps; 224 % 32 == 0
constexpr int BLOCKS  = (NCH + THREADS - 1) / THREADS;   // 147

__global__ void __launch_bounds__(THREADS)
indrnn_kernel(const float* __restrict__ x,
              const float* __restrict__ w_hh,
              const float* __restrict__ h0,
              float* __restrict__ out)
{
    const int ch = blockIdx.x * THREADS + threadIdx.x;
    if (ch >= NCH) return;   // only last block, warp-uniform (224|32768-32704)

    const float w = __ldg(&w_hh[ch & (HIDDEN - 1)]);
    float h = h0[ch];

    const float* xp = x + ch;
    float*       op = out + ch;

    float bufA[UNROLL];
    float bufB[UNROLL];

    // Prime buffer A with timesteps [0, UNROLL). Streaming loads: x is
    // touch-once (256 MB > L2), evict-first.
    #pragma unroll
    for (int i = 0; i < UNROLL; ++i)
        bufA[i] = __ldcs(xp + (size_t)i * NCH);

    // 2*UNROLL = 64 timesteps per iteration, 32 iterations exactly.
    #pragma unroll 1
    for (int t0 = 0; t0 < LEN; t0 += 2 * UNROLL) {
        // Fill B: timesteps [t0+UNROLL, t0+2*UNROLL)
        #pragma unroll
        for (int i = 0; i < UNROLL; ++i)
            bufB[i] = __ldcs(xp + (size_t)(t0 + UNROLL + i) * NCH);

        // Drain A: serial chain over [t0, t0+UNROLL)
        #pragma unroll
        for (int i = 0; i < UNROLL; ++i) {
            h = fmaxf(fmaf(h, w, bufA[i]), 0.0f);
            __stcs(op + (size_t)(t0 + i) * NCH, h);
        }

        // Refill A for the next iteration: [t0+2U, t0+3U). Uniform branch;
        // drops out entirely on the last iteration.
        const int tn = t0 + 2 * UNROLL;
        if (tn < LEN) {
            #pragma unroll
            for (int i = 0; i < UNROLL; ++i)
                bufA[i] = __ldcs(xp + (size_t)(tn + i) * NCH);
        }

        // Drain B: [t0+UNROLL, t0+2*UNROLL)
        #pragma unroll
        for (int i = 0; i < UNROLL; ++i) {
            h = fmaxf(fmaf(h, w, bufB[i]), 0.0f);
            __stcs(op + (size_t)(t0 + UNROLL + i) * NCH, h);
        }
    }
}

extern "C" void kernel_launch(void* const* d_in, const int* in_sizes, int n_in,
                              void* d_out, int out_size)
{
    const float* x    = (const float*)d_in[0];   // [LEN, BATCH, HIDDEN]
    const float* w_hh = (const float*)d_in[1];   // [HIDDEN]
    const float* h0   = (const float*)d_in[2];   // [BATCH, HIDDEN]
    float*       out  = (float*)d_out;           // [LEN, BATCH, HIDDEN]

    indrnn_kernel<<<BLOCKS, THREADS>>>(x, w_hh, h0, out);
}

// round 7
// speedup vs baseline: 1.0767x; 1.0767x over previous
#include <cuda_runtime.h>

// IndRNN recurrence: h_t = relu(h_{t-1} * w_hh + x_t), elementwise over
// 32*1024 = 32768 independent channels, 2048 timesteps.
// Pure streaming: 256 MB in + 256 MB out -> HBM-bound.
//
// One thread per channel (lane-adjacent -> coalesced 128B warp-loads).
// Recurrence serial in t; x[t] loads independent of h -> register
// ping-pong keeps UNROLL loads/thread in flight.
//
// History:
//  R3: launch_bounds reg cap killed MLP -> 370us, DRAM 16%.
//  R4: cap off, UNROLL=20 -> 112.7us, DRAM 54%.
//  R5: UNROLL=32, 256x128 grid -> 100.4us, DRAM 62%.
//  R6: 147x224 grid balance -> 102.4us NEUTRAL; in-flight bytes, not SM
//      balance, is binding. Reverted grid.
//  R7: UNROLL=48 (stays under M_max~55 outstanding LDG/warp so the fill
//      burst never stalls issue and blocks the drain). In-flight 6.3MB.

constexpr int LEN    = 2048;
constexpr int BATCH  = 32;
constexpr int HIDDEN = 1024;
constexpr int NCH    = BATCH * HIDDEN;   // 32768 channels
constexpr int UNROLL = 48;               // timesteps per buffer half
constexpr int MAIN   = (LEN / (2 * UNROLL)) * (2 * UNROLL);   // 2016
static_assert(LEN - MAIN <= UNROLL, "tail must fit in one buffer");

__global__ void __launch_bounds__(128)
indrnn_kernel(const float* __restrict__ x,
              const float* __restrict__ w_hh,
              const float* __restrict__ h0,
              float* __restrict__ out)
{
    const int ch = blockIdx.x * blockDim.x + threadIdx.x;   // exact coverage

    const float w = __ldg(&w_hh[ch & (HIDDEN - 1)]);
    float h = h0[ch];

    const float* xp = x + ch;
    float*       op = out + ch;

    float bufA[UNROLL];
    float bufB[UNROLL];

    // Prime buffer A with timesteps [0, UNROLL). Streaming: x is touch-once.
    #pragma unroll
    for (int i = 0; i < UNROLL; ++i)
        bufA[i] = __ldcs(xp + (size_t)i * NCH);

    // 2*UNROLL = 96 timesteps per iteration, 21 iterations -> 2016 steps.
    #pragma unroll 1
    for (int t0 = 0; t0 < MAIN; t0 += 2 * UNROLL) {
        // Fill B: timesteps [t0+UNROLL, t0+2*UNROLL)  (always in range)
        #pragma unroll
        for (int i = 0; i < UNROLL; ++i)
            bufB[i] = __ldcs(xp + (size_t)(t0 + UNROLL + i) * NCH);

        // Drain A: serial chain over [t0, t0+UNROLL)
        #pragma unroll
        for (int i = 0; i < UNROLL; ++i) {
            h = fmaxf(fmaf(h, w, bufA[i]), 0.0f);
            __stcs(op + (size_t)(t0 + i) * NCH, h);
        }

        // Refill A: [t0+2U, t0+3U) — predicated per element so the final
        // iteration loads only the real tail [2016, 2048).
        const int tn = t0 + 2 * UNROLL;
        #pragma unroll
        for (int i = 0; i < UNROLL; ++i)
            if (tn + i < LEN)
                bufA[i] = __ldcs(xp + (size_t)(tn + i) * NCH);

        // Drain B: [t0+UNROLL, t0+2*UNROLL)
        #pragma unroll
        for (int i = 0; i < UNROLL; ++i) {
            h = fmaxf(fmaf(h, w, bufB[i]), 0.0f);
            __stcs(op + (size_t)(t0 + UNROLL + i) * NCH, h);
        }
    }

    // Tail: timesteps [MAIN, LEN) sit in bufA[0 .. LEN-MAIN).
    #pragma unroll
    for (int i = 0; i < LEN - MAIN; ++i) {
        h = fmaxf(fmaf(h, w, bufA[i]), 0.0f);
        __stcs(op + (size_t)(MAIN + i) * NCH, h);
    }
}

extern "C" void kernel_launch(void* const* d_in, const int* in_sizes, int n_in,
                              void* d_out, int out_size)
{
    const float* x    = (const float*)d_in[0];   // [LEN, BATCH, HIDDEN]
    const float* w_hh = (const float*)d_in[1];   // [HIDDEN]
    const float* h0   = (const float*)d_in[2];   // [BATCH, HIDDEN]
    float*       out  = (float*)d_out;           // [LEN, BATCH, HIDDEN]

    const int threads = 128;
    const int blocks  = NCH / threads;           // 256 blocks
    indrnn_kernel<<<blocks, threads>>>(x, w_hh, h0, out);
}